// round 8
// baseline (speedup 1.0000x reference)
#include <cuda_runtime.h>
#include <cuda_bf16.h>
#include <math.h>

// ---------------- problem constants ----------------
#define B_SZ   256
#define T_SZ   512
#define HID    300
#define EMB    300
#define VOCAB  50000
#define NCLS   5
#define GATES  1200        // 4*HID
#define PCOLS  2400        // 2*GATES (A-part | B-part)

// recurrence persistent-kernel tiling
#define NCTA   120         // 8 bt-groups x 15 u-tiles (1 CTA/SM, all resident)
#define BT     32          // batch rows per CTA
#define HBT    16          // half-batch (pipelined)
#define UT     20          // hidden units per CTA
#define RT     80          // 4 gates * UT rows per CTA
#define WSTR   302         // Wt row stride (floats): conflict-free LDS.64
#define GPSU   84          // gp row stride (u64 units)
#define HBYTES (HBT * HID * 4)   // 19200 B per half TMA

typedef unsigned long long u64;
typedef unsigned int u32;

// ---------------- f32x2 packed math (exact fp32 FMA/add semantics) -----------
__device__ __forceinline__ void ffma2(u64& d, u64 a, u64 b) {
    asm("fma.rn.f32x2 %0, %1, %2, %0;" : "+l"(d) : "l"(a), "l"(b));
}
__device__ __forceinline__ u64 add2(u64 a, u64 b) {
    u64 r; asm("add.rn.f32x2 %0, %1, %2;" : "=l"(r) : "l"(a), "l"(b)); return r;
}
__device__ __forceinline__ u64 dup2(float x) {
    u64 r; asm("mov.b64 %0, {%1, %1};" : "=l"(r) : "f"(x)); return r;
}
__device__ __forceinline__ float2 unpack2(u64 v) {
    float2 f; asm("mov.b64 {%0, %1}, %2;" : "=f"(f.x), "=f"(f.y) : "l"(v)); return f;
}

// ---------------- fast activations (MUFU-based) ------------------------------
__device__ __forceinline__ float fsig(float x) {
    return __fdividef(1.f, 1.f + __expf(-x));
}

// ---------------- static device scratch (no allocations allowed) -------------
__device__ float d_P[(long long)VOCAB * PCOLS];      // 480 MB: glove @ [A|B]^T
__device__ float d_Wcat[PCOLS * EMB];                // repacked W_ih
__device__ __align__(256) float d_h[2 * B_SZ * HID]; // double-buffered h
__device__ float d_hsum[B_SZ * HID];                 // sum_t h_t
__device__ u32 d_arrive[8][2][16];                   // per (bt-group, half) flags

// ---------------- prep: repack W_ih, zero h0, reset flags --------------------
__global__ void prep_kernel(const float* __restrict__ W_ih,
                            float* __restrict__ Wcat,
                            float* __restrict__ h0) {
    int i = blockIdx.x * blockDim.x + threadIdx.x;
    if (i < PCOLS * EMB) {
        int n = i / EMB, k = i % EMB;
        Wcat[i] = (n < GATES) ? W_ih[n * 600 + k]
                              : W_ih[(n - GATES) * 600 + 300 + k];
    }
    if (i < B_SZ * HID) h0[i] = 0.f;
    if (i < 256) ((u32*)d_arrive)[i] = 0u;
}

// ---------------- C = A @ B^T with packed f32x2 FMA (verified) ----------------
#define TILE 128
#define KB   10
__global__ __launch_bounds__(256)
void sgemm_f2(const float* __restrict__ A, const float* __restrict__ B,
              float* __restrict__ C,
              int M, int N, int Klen, int lda, int ldb, int ldc) {
    __shared__ __align__(16) float As[KB][TILE + 4];
    __shared__ __align__(16) float Bs[KB][TILE + 4];

    const int m0 = blockIdx.y * TILE;
    const int n0 = blockIdx.x * TILE;
    const int tid = threadIdx.x;
    const int tx = tid & 15;
    const int ty = tid >> 4;

    u64 acc[8][4];
#pragma unroll
    for (int i = 0; i < 8; i++)
#pragma unroll
        for (int p = 0; p < 4; p++) acc[i][p] = 0ULL;

    for (int kk = 0; kk < Klen; kk += KB) {
#pragma unroll
        for (int it = 0; it < (TILE * KB) / 256; it++) {
            int idx = tid + it * 256;
            int k = idx % KB;
            int m = idx / KB;
            int gm = m0 + m;
            float v = 0.f;
            if (gm < M) v = A[(long long)gm * lda + (kk + k)];
            As[k][m] = v;
        }
#pragma unroll
        for (int it = 0; it < (TILE * KB) / 256; it++) {
            int idx = tid + it * 256;
            int k = idx % KB;
            int n = idx / KB;
            int gn = n0 + n;
            float v = 0.f;
            if (gn < N) v = B[(long long)gn * ldb + (kk + k)];
            Bs[k][n] = v;
        }
        __syncthreads();

#pragma unroll
        for (int kb = 0; kb < KB; kb++) {
            u64 ad[8], bd[4];
#pragma unroll
            for (int i = 0; i < 8; i++) ad[i] = dup2(As[kb][ty * 8 + i]);
#pragma unroll
            for (int p = 0; p < 4; p++)
                bd[p] = *(const u64*)&Bs[kb][2 * tx + 32 * p];
#pragma unroll
            for (int i = 0; i < 8; i++)
#pragma unroll
                for (int p = 0; p < 4; p++)
                    ffma2(acc[i][p], ad[i], bd[p]);
        }
        __syncthreads();
    }

#pragma unroll
    for (int i = 0; i < 8; i++) {
        int gm = m0 + ty * 8 + i;
        if (gm < M) {
#pragma unroll
            for (int p = 0; p < 4; p++) {
                int gn = n0 + 2 * tx + 32 * p;
                if (gn < N)
                    *(u64*)&C[(long long)gm * ldc + gn] = acc[i][p];
            }
        }
    }
}

// ---------------- acquire/release + TMA helpers -------------------------------
__device__ __forceinline__ u32 ld_acq(const u32* p) {
    u32 v;
    asm volatile("ld.global.acquire.gpu.u32 %0, [%1];" : "=r"(v) : "l"(p));
    return v;
}
__device__ __forceinline__ void st_rel(u32* p, u32 v) {
    asm volatile("st.global.release.gpu.u32 [%0], %1;" :: "l"(p), "r"(v));
}
__device__ __forceinline__ u32 smem_u32(const void* p) {
    u32 a;
    asm("{ .reg .u64 t; cvta.to.shared.u64 t, %1; cvt.u32.u64 %0, t; }"
        : "=r"(a) : "l"(p));
    return a;
}
__device__ __forceinline__ void mbar_init(u32 mbar, u32 cnt) {
    asm volatile("mbarrier.init.shared.b64 [%0], %1;" :: "r"(mbar), "r"(cnt) : "memory");
}
__device__ __forceinline__ void mbar_expect_tx(u32 mbar, u32 bytes) {
    asm volatile("mbarrier.arrive.expect_tx.shared.b64 _, [%0], %1;"
                 :: "r"(mbar), "r"(bytes) : "memory");
}
__device__ __forceinline__ void bulk_cp_g2s(u32 dst, const void* src, u32 bytes, u32 mbar) {
    asm volatile("cp.async.bulk.shared::cluster.global.mbarrier::complete_tx::bytes "
                 "[%0], [%1], %2, [%3];"
                 :: "r"(dst), "l"(src), "r"(bytes), "r"(mbar) : "memory");
}
__device__ __forceinline__ void mbar_wait(u32 mbar, u32 parity) {
    asm volatile(
        "{\n\t.reg .pred P;\n\t"
        "W_%=:\n\t"
        "mbarrier.try_wait.parity.acquire.cta.shared::cta.b64 P, [%0], %1;\n\t"
        "@!P bra W_%=;\n\t}"
        :: "r"(mbar), "r"(parity) : "memory");
}

// ---------------- persistent recurrence kernel --------------------------------
// 120 CTAs x 512 threads. Two phase-shifted 16-row batch halves per CTA:
// while half ph computes step t, half ph^1's flag-poll + TMA are in flight.
// GEMM per iteration: 16b x 80r x 300k, 16 warps (4 k-splits x 4 subtiles),
// thread tile 2b x 5r, k-pair-packed f32x2 FMA (LDS.64 operands throughout).
#define SM_WT   (RT * WSTR)                 // 24160 floats
#define SM_H    (2 * HBT * HID)             // 9600 floats
#define SM_GP   (4 * HBT * GPSU * 2)        // 10752 floats (u64 array)
#define SM_FLOATS (SM_WT + SM_H + SM_GP)    // 44512
#define SM_BYTES  (SM_FLOATS * 4 + 16)      // + 2 mbarriers

__global__ __launch_bounds__(512, 1)
void lstm_persistent(const float* __restrict__ W_hh,
                     const float* __restrict__ P,
                     const int* __restrict__ ids,
                     const float* __restrict__ b_ih,
                     const float* __restrict__ b_hh,
                     float* __restrict__ hbuf,
                     float* __restrict__ hsum) {
    extern __shared__ __align__(16) float sm[];
    float* Wt   = sm;                        // [80][302] r-major
    float* hsm  = sm + SM_WT;                // [2][16][300]
    u64*   gp64 = (u64*)(hsm + SM_H);        // [4][16][84]

    const int tid = threadIdx.x;
    const int bt  = blockIdx.x & 7;          // independent bt-group
    const int ut  = blockIdx.x >> 3;         // 0..14
    const int b0c = bt * BT;
    const int u0  = ut * UT;

    const u32 hsm_s = smem_u32(hsm);
    const u32 mbar0 = smem_u32(sm) + SM_FLOATS * 4;
    const u32 mbar1 = mbar0 + 8;

    if (tid == 0) { mbar_init(mbar0, 1); mbar_init(mbar1, 1); }

    // ---- load this CTA's 80 W_hh rows into smem, r-major (k contiguous) ----
    for (int idx = tid; idx < RT * HID; idx += 512) {
        int r = idx / HID;
        int k = idx - r * HID;
        int g = r / UT;
        int du = r - g * UT;
        Wt[r * WSTR + k] = W_hh[(g * HID + u0 + du) * HID + k];
    }

    // ---- GEMM mapping: 16 warps = 4 k-splits x 4 (bo,ro) subtiles ----
    const int lane = tid & 31;
    const int wrp  = tid >> 5;
    const int kz   = wrp & 3;
    const int quad = wrp >> 2;
    const int bo   = (quad & 1) * 8;
    const int ro   = (quad >> 1) * 40;
    const int gtx  = lane & 3;               // b = bo + gtx + 4i, i<2
    const int gty  = lane >> 2;              // r = ro + gty*5 + q, q<5
    // even-aligned K chunks: [0,76) [76,150) [150,226) [226,300)
    const int kbeg  = kz * 75 + (kz & 1);
    const int npair = 38 - (kz & 1);

    // ---- pointwise ownership: 320 cells/half, 1 per thread (tid<320) ----
    const bool pw = (tid < HBT * UT);
    const int bl = tid / UT;
    const int du = tid - bl * UT;
    float bs[4];
#pragma unroll
    for (int g = 0; g < 4; g++) {
        int col = g * HID + u0 + du;
        bs[g] = pw ? (b_ih[col] + b_hh[col]) : 0.f;
    }
    float cr[2] = {0.f, 0.f};
    float hs[2] = {0.f, 0.f};

    __syncthreads();

    // ---- preload both halves' h for t=0 (hbuf[0] zeroed by prep) ----
    if (tid == 0) {
        mbar_expect_tx(mbar0, HBYTES);
        bulk_cp_g2s(hsm_s, hbuf + (long long)b0c * HID, HBYTES, mbar0);
        mbar_expect_tx(mbar1, HBYTES);
        bulk_cp_g2s(hsm_s + HBYTES, hbuf + (long long)(b0c + HBT) * HID,
                    HBYTES, mbar1);
    }

    for (int it = 0; it < 2 * T_SZ; it++) {
        const int ph = it & 1;
        const int t  = it >> 1;
        const u32 mbar = ph ? mbar1 : mbar0;
        float* hout = hbuf + ((t + 1) & 1) * (B_SZ * HID);

        // ---- prefetch P gathers for this half (overlaps TMA wait + GEMM) ----
        float pfA[4] = {0.f, 0.f, 0.f, 0.f};
        float pfB[4] = {0.f, 0.f, 0.f, 0.f};
        if (pw) {
            int gb = b0c + ph * HBT + bl;
            if (t != T_SZ - 1) {              // emb[T-1] zeroed (reference quirk)
                const float* pa = P + (long long)ids[gb * T_SZ + t] * PCOLS
                                    + u0 + du;
#pragma unroll
                for (int g = 0; g < 4; g++) pfA[g] = pa[g * HID];
            }
            if (t != 0) {                     // emb_{-1} is zero padding
                const float* pb = P + (long long)ids[gb * T_SZ + t - 1] * PCOLS
                                    + GATES + u0 + du;
#pragma unroll
                for (int g = 0; g < 4; g++) pfB[g] = pb[g * HID];
            }
        }

        // ---- wait for this half's h tile (TMA'd one iteration ago) ----
        mbar_wait(mbar, (u32)(t & 1));

        // ---- gates GEMM: 16b x 80r, k-pair-packed f32x2 ----
        {
            const float* hb = hsm + ph * (HBT * HID) + (bo + gtx) * HID;
            const float* wb = Wt + (ro + gty * 5) * WSTR;
            u64 acc[2][5];
#pragma unroll
            for (int i = 0; i < 2; i++)
#pragma unroll
                for (int q = 0; q < 5; q++) acc[i][q] = 0ULL;

#pragma unroll 2
            for (int p = 0; p < npair; p++) {
                int k = kbeg + 2 * p;
                u64 h0 = *(const u64*)(hb + k);
                u64 h1 = *(const u64*)(hb + 4 * HID + k);
                u64 w2[5];
#pragma unroll
                for (int q = 0; q < 5; q++)
                    w2[q] = *(const u64*)(wb + q * WSTR + k);
#pragma unroll
                for (int q = 0; q < 5; q++) {
                    ffma2(acc[0][q], h0, w2[q]);
                    ffma2(acc[1][q], h1, w2[q]);
                }
            }
            u64* g0 = gp64 + (kz * HBT + bo + gtx) * GPSU + ro + gty * 5;
#pragma unroll
            for (int q = 0; q < 5; q++) {
                g0[q] = acc[0][q];
                g0[4 * GPSU + q] = acc[1][q];
            }
        }
        __syncthreads();

        // ---- fused cell update: reduce 4 kz-pairs + P + activations ----
        if (pw) {
            float g4[4];
#pragma unroll
            for (int g = 0; g < 4; g++) {
                int r = g * UT + du;
                u64 s0 = gp64[(0 * HBT + bl) * GPSU + r];
                u64 s1 = gp64[(1 * HBT + bl) * GPSU + r];
                u64 s2 = gp64[(2 * HBT + bl) * GPSU + r];
                u64 s3 = gp64[(3 * HBT + bl) * GPSU + r];
                float2 f = unpack2(add2(add2(s0, s1), add2(s2, s3)));
                g4[g] = f.x + f.y + bs[g] + pfA[g] + pfB[g];
            }
            float ig = fsig(g4[0]);
            float fg = fsig(g4[1]);
            float gg = 2.f * fsig(2.f * g4[2]) - 1.f;   // tanh
            float og = fsig(g4[3]);
            cr[ph] = fg * cr[ph] + ig * gg;
            float hv = og * (2.f * fsig(2.f * cr[ph]) - 1.f);
            hout[(b0c + ph * HBT + bl) * HID + u0 + du] = hv;
            hs[ph] += hv;
        }
        __syncthreads();

        // ---- signal + group-poll + issue TMA for (ph, t+1) [warp 0 only] ----
        if (t + 1 < T_SZ && wrp == 0) {
            if (lane == 0) st_rel(&d_arrive[bt][ph][ut], (u32)(t + 1));
            if (lane < 15) {
                while (ld_acq(&d_arrive[bt][ph][lane]) < (u32)(t + 1)) {}
            }
            __syncwarp();
            if (lane == 0) {
                mbar_expect_tx(mbar, HBYTES);
                bulk_cp_g2s(hsm_s + ph * HBYTES,
                            hout + (long long)(b0c + ph * HBT) * HID,
                            HBYTES, mbar);
            }
        }
        // other warps fall through to next iteration (guarded by mbar_wait)
    }

    // ---- write hidden-state sums for the classifier ----
    if (pw) {
        hsum[(b0c + bl) * HID + u0 + du] = hs[0];
        hsum[(b0c + HBT + bl) * HID + u0 + du] = hs[1];
    }
}

// ---------------- classifier head: mean-pool -> dense(100) -> dense(5) -> LSM
__global__ void classifier(const float* __restrict__ hsum,
                           const float* __restrict__ W1, const float* __restrict__ b1,
                           const float* __restrict__ W2, const float* __restrict__ b2,
                           float* __restrict__ out) {
    int b = blockIdx.x;
    int tid = threadIdx.x;   // 128
    __shared__ float pooled[HID];
    __shared__ float l1s[100];
    __shared__ float l2s[NCLS];

    for (int i = tid; i < HID; i += blockDim.x)
        pooled[i] = hsum[b * HID + i] * (1.f / (float)T_SZ);
    __syncthreads();

    if (tid < 100) {
        float s = b1[tid];
        const float* wr = W1 + tid * HID;
#pragma unroll 4
        for (int k = 0; k < HID; k++) s = fmaf(pooled[k], wr[k], s);
        l1s[tid] = 1.f / (1.f + expf(-s));
    }
    __syncthreads();

    if (tid < NCLS) {
        float s = b2[tid];
        const float* wr = W2 + tid * 100;
#pragma unroll 4
        for (int k = 0; k < 100; k++) s = fmaf(l1s[k], wr[k], s);
        l2s[tid] = 1.f / (1.f + expf(-s));
    }
    __syncthreads();

    if (tid < NCLS) {
        float m = l2s[0];
#pragma unroll
        for (int j = 1; j < NCLS; j++) m = fmaxf(m, l2s[j]);
        float sum = 0.f;
#pragma unroll
        for (int j = 0; j < NCLS; j++) sum += expf(l2s[j] - m);
        out[b * NCLS + tid] = l2s[tid] - m - logf(sum);
    }
}

// ------------------------------ launch ---------------------------------------
extern "C" void kernel_launch(void* const* d_in, const int* in_sizes, int n_in,
                              void* d_out, int out_size) {
    const int*   ids  = nullptr;
    const float* glove = nullptr, *W_ih = nullptr, *W_hh = nullptr;
    const float* b_ih = nullptr, *b_hh = nullptr;
    const float* W1 = nullptr, *b1 = nullptr, *W2 = nullptr, *b2 = nullptr;

    for (int i = 0; i < n_in; i++) {
        switch (in_sizes[i]) {
            case B_SZ * T_SZ:      ids   = (const int*)d_in[i];   break;
            case VOCAB * EMB:      glove = (const float*)d_in[i]; break;
            case GATES * 600:      W_ih  = (const float*)d_in[i]; break;
            case GATES * HID:      W_hh  = (const float*)d_in[i]; break;
            case GATES:            if (!b_ih) b_ih = (const float*)d_in[i];
                                   else       b_hh = (const float*)d_in[i]; break;
            case 100 * HID:        W1 = (const float*)d_in[i]; break;
            case 100:              b1 = (const float*)d_in[i]; break;
            case NCLS * 100:       W2 = (const float*)d_in[i]; break;
            case NCLS:             b2 = (const float*)d_in[i]; break;
            default: break; // size-1 scalar (max_num_of_words) ignored
        }
    }
    if (!ids || !glove || !W_ih || !W_hh || !b_ih || !b_hh || !W1 || !b1 || !W2 || !b2)
        return;

    float *P, *Wcat, *hbuf, *hsum;
    cudaGetSymbolAddress((void**)&P,    d_P);
    cudaGetSymbolAddress((void**)&Wcat, d_Wcat);
    cudaGetSymbolAddress((void**)&hbuf, d_h);
    cudaGetSymbolAddress((void**)&hsum, d_hsum);

    static bool attr_done = false;
    if (!attr_done) {
        cudaFuncSetAttribute(lstm_persistent,
                             cudaFuncAttributeMaxDynamicSharedMemorySize,
                             SM_BYTES);
        attr_done = true;
    }

    // 1) repack W_ih, zero h0 + flags               [1 node]
    prep_kernel<<<(PCOLS * EMB + 255) / 256, 256>>>(W_ih, Wcat, hbuf);

    // 2) vocabulary projection P = glove @ Wcat^T   [1 node]
    {
        dim3 grid((PCOLS + TILE - 1) / TILE, (VOCAB + TILE - 1) / TILE, 1);
        sgemm_f2<<<grid, 256>>>(glove, Wcat, P,
                                VOCAB, PCOLS, EMB, EMB, EMB, PCOLS);
    }

    // 3) whole 512-step LSTM, half-batch pipelined  [1 node]
    lstm_persistent<<<NCTA, 512, SM_BYTES>>>(
        W_hh, P, ids, b_ih, b_hh, hbuf, hsum);

    // 4) classifier head                            [1 node]
    classifier<<<B_SZ, 128>>>(hsum, W1, b1, W2, b2, (float*)d_out);
}

// round 9
// speedup vs baseline: 1.0603x; 1.0603x over previous
#include <cuda_runtime.h>
#include <cuda_bf16.h>
#include <math.h>

// ---------------- problem constants ----------------
#define B_SZ   256
#define T_SZ   512
#define HID    300
#define EMB    300
#define VOCAB  50000
#define NCLS   5
#define GATES  1200        // 4*HID
#define PCOLS  2400        // 2*GATES (A-part | B-part)

// recurrence persistent-kernel tiling
#define NCTA   120         // 8 bt-groups x 15 u-tiles (1 CTA/SM, all resident)
#define BT     32          // batch rows per CTA
#define UT     20          // hidden units per CTA
#define RT     80          // 4 gates * UT rows per CTA
#define HHALF  150         // k half
#define HBLK   (BT * HHALF)        // 4800 floats per (bt, khalf) block
#define HBLKB  (HBLK * 4)          // 19200 bytes
#define WSTR   302                 // Wt row stride (floats), conflict-free LDS.64
#define GPSU   84                  // gp row stride in u64 units

typedef unsigned long long u64;
typedef unsigned int u32;

// ---------------- f32x2 packed math (exact fp32 FMA/add semantics) -----------
__device__ __forceinline__ void ffma2(u64& d, u64 a, u64 b) {
    asm("fma.rn.f32x2 %0, %1, %2, %0;" : "+l"(d) : "l"(a), "l"(b));
}
__device__ __forceinline__ u64 add2(u64 a, u64 b) {
    u64 r; asm("add.rn.f32x2 %0, %1, %2;" : "=l"(r) : "l"(a), "l"(b)); return r;
}
__device__ __forceinline__ u64 dup2(float x) {
    u64 r; asm("mov.b64 %0, {%1, %1};" : "=l"(r) : "f"(x)); return r;
}
__device__ __forceinline__ float2 unpack2(u64 v) {
    float2 f; asm("mov.b64 {%0, %1}, %2;" : "=f"(f.x), "=f"(f.y) : "l"(v)); return f;
}

// ---------------- fast activations (MUFU-based) ------------------------------
__device__ __forceinline__ float fsig(float x) {
    return __fdividef(1.f, 1.f + __expf(-x));
}

// ---------------- static device scratch (no allocations allowed) -------------
__device__ float d_P[(long long)VOCAB * PCOLS];      // 480 MB: glove @ [A|B]^T
__device__ float d_Wcat[PCOLS * EMB];                // repacked W_ih
// h exchange buffer: [parity][khalf][bt][32][150] (contiguous 19200B blocks)
__device__ __align__(256) float d_hx[2 * 2 * 8 * HBLK];
__device__ float d_hsum[B_SZ * HID];                 // sum_t h_t
__device__ u32 d_arrive[8][16];                      // per-bt-group flags

// ---------------- prep: repack W_ih, zero h-exchange, reset flags ------------
__global__ void prep_kernel(const float* __restrict__ W_ih,
                            float* __restrict__ Wcat,
                            float* __restrict__ hx) {
    int i = blockIdx.x * blockDim.x + threadIdx.x;
    if (i < PCOLS * EMB) {
        int n = i / EMB, k = i % EMB;
        Wcat[i] = (n < GATES) ? W_ih[n * 600 + k]
                              : W_ih[(n - GATES) * 600 + 300 + k];
    }
    if (i < 2 * 2 * 8 * HBLK) hx[i] = 0.f;
    if (i < 128) ((u32*)d_arrive)[i] = 0u;
}

// ---------------- C = A @ B^T with packed f32x2 FMA (verified R5-R7) ----------
#define TILE 128
#define KB   10
__global__ __launch_bounds__(256)
void sgemm_f2(const float* __restrict__ A, const float* __restrict__ B,
              float* __restrict__ C,
              int M, int N, int Klen, int lda, int ldb, int ldc) {
    __shared__ __align__(16) float As[KB][TILE + 4];
    __shared__ __align__(16) float Bs[KB][TILE + 4];

    const int m0 = blockIdx.y * TILE;
    const int n0 = blockIdx.x * TILE;
    const int tid = threadIdx.x;
    const int tx = tid & 15;
    const int ty = tid >> 4;

    u64 acc[8][4];
#pragma unroll
    for (int i = 0; i < 8; i++)
#pragma unroll
        for (int p = 0; p < 4; p++) acc[i][p] = 0ULL;

    for (int kk = 0; kk < Klen; kk += KB) {
#pragma unroll
        for (int it = 0; it < (TILE * KB) / 256; it++) {
            int idx = tid + it * 256;
            int k = idx % KB;
            int m = idx / KB;
            int gm = m0 + m;
            float v = 0.f;
            if (gm < M) v = A[(long long)gm * lda + (kk + k)];
            As[k][m] = v;
        }
#pragma unroll
        for (int it = 0; it < (TILE * KB) / 256; it++) {
            int idx = tid + it * 256;
            int k = idx % KB;
            int n = idx / KB;
            int gn = n0 + n;
            float v = 0.f;
            if (gn < N) v = B[(long long)gn * ldb + (kk + k)];
            Bs[k][n] = v;
        }
        __syncthreads();

#pragma unroll
        for (int kb = 0; kb < KB; kb++) {
            u64 ad[8], bd[4];
#pragma unroll
            for (int i = 0; i < 8; i++) ad[i] = dup2(As[kb][ty * 8 + i]);
#pragma unroll
            for (int p = 0; p < 4; p++)
                bd[p] = *(const u64*)&Bs[kb][2 * tx + 32 * p];
#pragma unroll
            for (int i = 0; i < 8; i++)
#pragma unroll
                for (int p = 0; p < 4; p++)
                    ffma2(acc[i][p], ad[i], bd[p]);
        }
        __syncthreads();
    }

#pragma unroll
    for (int i = 0; i < 8; i++) {
        int gm = m0 + ty * 8 + i;
        if (gm < M) {
#pragma unroll
            for (int p = 0; p < 4; p++) {
                int gn = n0 + 2 * tx + 32 * p;
                if (gn < N)
                    *(u64*)&C[(long long)gm * ldc + gn] = acc[i][p];
            }
        }
    }
}

// ---------------- acquire/release + TMA helpers -------------------------------
__device__ __forceinline__ u32 ld_acq(const u32* p) {
    u32 v;
    asm volatile("ld.global.acquire.gpu.u32 %0, [%1];" : "=r"(v) : "l"(p));
    return v;
}
__device__ __forceinline__ void st_rel(u32* p, u32 v) {
    asm volatile("st.global.release.gpu.u32 [%0], %1;" :: "l"(p), "r"(v));
}
__device__ __forceinline__ u32 smem_u32(const void* p) {
    u32 a;
    asm("{ .reg .u64 t; cvta.to.shared.u64 t, %1; cvt.u32.u64 %0, t; }"
        : "=r"(a) : "l"(p));
    return a;
}
__device__ __forceinline__ void mbar_init(u32 mbar, u32 cnt) {
    asm volatile("mbarrier.init.shared.b64 [%0], %1;" :: "r"(mbar), "r"(cnt) : "memory");
}
__device__ __forceinline__ void mbar_expect_tx(u32 mbar, u32 bytes) {
    asm volatile("mbarrier.arrive.expect_tx.shared.b64 _, [%0], %1;"
                 :: "r"(mbar), "r"(bytes) : "memory");
}
__device__ __forceinline__ void bulk_cp_g2s(u32 dst, const void* src, u32 bytes, u32 mbar) {
    asm volatile("cp.async.bulk.shared::cluster.global.mbarrier::complete_tx::bytes "
                 "[%0], [%1], %2, [%3];"
                 :: "r"(dst), "l"(src), "r"(bytes), "r"(mbar) : "memory");
}
__device__ __forceinline__ void mbar_wait(u32 mbar, u32 parity) {
    asm volatile(
        "{\n\t.reg .pred P;\n\t"
        "W_%=:\n\t"
        "mbarrier.try_wait.parity.acquire.cta.shared::cta.b64 P, [%0], %1;\n\t"
        "@!P bra W_%=;\n\t}"
        :: "r"(mbar), "r"(parity) : "memory");
}

// ---------------- persistent recurrence kernel --------------------------------
// 120 CTAs x 256 threads (R7 structure). Per step:
//   two TMA halves (k<150 / k>=150) -> kz0/kz1 warps wait their own half
//   GEMM 32b x 80r, k-pair-packed f32x2 (LDS.64 everywhere), 8 warps
//   pointwise: u64 gp reduce + prefetched P + fast activations
//   warp0-only: release flag, poll 15 peers, issue next step's 2 TMAs
#define SM_WT   (RT * WSTR)                 // 24160 floats
#define SM_H    (2 * HBLK)                  // 9600 floats (lo | hi)
#define SM_GPU  (2 * BT * GPSU)             // 5376 u64
#define SM_FLOATS (SM_WT + SM_H + 2 * SM_GPU)   // 44512
#define SM_BYTES  (SM_FLOATS * 4 + 16)          // + 2 mbarriers

__global__ __launch_bounds__(256, 1)
void lstm_persistent(const float* __restrict__ W_hh,
                     const float* __restrict__ P,
                     const int* __restrict__ ids,
                     const float* __restrict__ b_ih,
                     const float* __restrict__ b_hh,
                     float* __restrict__ hx,
                     float* __restrict__ hsum) {
    extern __shared__ __align__(16) float sm[];
    float* Wt   = sm;                        // [80][302] r-major, k contiguous
    float* hsm  = sm + SM_WT;                // [2 khalf][32][150]
    u64*   gp64 = (u64*)(hsm + SM_H);        // [2 kz][32][84]

    const int tid = threadIdx.x;
    const int bt  = blockIdx.x & 7;          // independent bt-group
    const int ut  = blockIdx.x >> 3;         // 0..14
    const int b0c = bt * BT;
    const int u0  = ut * UT;

    const u32 hsm_s = smem_u32(hsm);
    const u32 mbar_lo = smem_u32(sm) + SM_FLOATS * 4;
    const u32 mbar_hi = mbar_lo + 8;

    if (tid == 0) { mbar_init(mbar_lo, 1); mbar_init(mbar_hi, 1); }

    // ---- load this CTA's 80 W_hh rows into smem, r-major (k contiguous) ----
    for (int idx = tid; idx < RT * HID; idx += 256) {
        int r = idx / HID;
        int k = idx - r * HID;
        int g = r / UT;
        int du = r - g * UT;
        Wt[r * WSTR + k] = W_hh[(g * HID + u0 + du) * HID + k];
    }

    // ---- GEMM mapping: 8 warps = 2 kz x 2 b-halves x 2 r-halves ----
    const int lane = tid & 31;
    const int wrp  = tid >> 5;
    const int kz   = wrp & 1;                // k half: [0,150) or [150,300)
    const int quad = wrp >> 1;
    const int bo   = (quad & 1) * 16;        // b base
    const int ro   = (quad >> 1) * 40;       // r base
    const int gtx  = lane & 3;               // b = bo + gtx + 4i, i<4
    const int gty  = lane >> 2;              // r = ro + gty*5 + q, q<5
    const u32 my_mbar = kz ? mbar_hi : mbar_lo;

    // ---- pointwise ownership: 3 cells per thread (cells tid, +256, +512) ----
    int bl[3], duc[3], hoff[3];
    bool actc[3];
#pragma unroll
    for (int c = 0; c < 3; c++) {
        int cell = tid + c * 256;
        bl[c] = cell / UT;
        duc[c] = cell - bl[c] * UT;
        actc[c] = (c < 2) || (tid < 128);
        int u = u0 + duc[c];
        int kh = (u >= HHALF);
        hoff[c] = ((kh * 8 + bt) * BT + bl[c]) * HHALF + (u - kh * HHALF);
    }
    float cr[3] = {0.f, 0.f, 0.f};
    float hs[3] = {0.f, 0.f, 0.f};
    float bs[3][4];
#pragma unroll
    for (int c = 0; c < 3; c++) {
#pragma unroll
        for (int g = 0; g < 4; g++) {
            int col = g * HID + u0 + duc[c];
            bs[c][g] = actc[c] ? (b_ih[col] + b_hh[col]) : 0.f;
        }
    }

    __syncthreads();

    // ---- initial TMAs: parity-0 h (zeroed by prep) ----
    if (tid == 0) {
        mbar_expect_tx(mbar_lo, HBLKB);
        bulk_cp_g2s(hsm_s, hx + (long long)bt * HBLK, HBLKB, mbar_lo);
        mbar_expect_tx(mbar_hi, HBLKB);
        bulk_cp_g2s(hsm_s + HBLKB, hx + (long long)(8 + bt) * HBLK,
                    HBLKB, mbar_hi);
    }

    for (int t = 0; t < T_SZ; t++) {
        float* hx_out = hx + ((t + 1) & 1) * (2 * 8 * HBLK);

        // ---- prefetch P gathers into registers (overlaps TMA wait + GEMM) ----
        float pfA[3][4], pfB[3][4];
#pragma unroll
        for (int c = 0; c < 3; c++) {
#pragma unroll
            for (int g = 0; g < 4; g++) { pfA[c][g] = 0.f; pfB[c][g] = 0.f; }
            if (actc[c]) {
                int row = (b0c + bl[c]) * T_SZ;
                if (t != T_SZ - 1) {          // emb[T-1] zeroed (reference quirk)
                    const float* pa = P + (long long)ids[row + t] * PCOLS
                                        + u0 + duc[c];
#pragma unroll
                    for (int g = 0; g < 4; g++) pfA[c][g] = pa[g * HID];
                }
                if (t != 0) {                 // emb_{-1} is zero padding
                    const float* pb = P + (long long)ids[row + t - 1] * PCOLS
                                        + GATES + u0 + duc[c];
#pragma unroll
                    for (int g = 0; g < 4; g++) pfB[c][g] = pb[g * HID];
                }
            }
        }

        // ---- wait only for this warp's k-half ----
        mbar_wait(my_mbar, (u32)(t & 1));

        // ---- gates GEMM: 32b x 80r, k-pair-packed f32x2 ----
        {
            const float* hb = hsm + kz * HBLK + (bo + gtx) * HHALF;
            const float* wb = Wt + (ro + gty * 5) * WSTR + kz * HHALF;
            u64 acc[4][5];
#pragma unroll
            for (int i = 0; i < 4; i++)
#pragma unroll
                for (int q = 0; q < 5; q++) acc[i][q] = 0ULL;

#pragma unroll 3
            for (int p = 0; p < HHALF / 2; p++) {
                int k = 2 * p;
                u64 hd[4], wd[5];
#pragma unroll
                for (int i = 0; i < 4; i++)
                    hd[i] = *(const u64*)(hb + i * 4 * HHALF + k);
#pragma unroll
                for (int q = 0; q < 5; q++)
                    wd[q] = *(const u64*)(wb + q * WSTR + k);
#pragma unroll
                for (int i = 0; i < 4; i++)
#pragma unroll
                    for (int q = 0; q < 5; q++)
                        ffma2(acc[i][q], hd[i], wd[q]);
            }
            u64* g0 = gp64 + (kz * BT + bo + gtx) * GPSU + ro + gty * 5;
#pragma unroll
            for (int i = 0; i < 4; i++)
#pragma unroll
                for (int q = 0; q < 5; q++)
                    g0[i * 4 * GPSU + q] = acc[i][q];
        }
        __syncthreads();

        // ---- fused cell update: u64 gp reduce + prefetched P + activations --
#pragma unroll
        for (int c = 0; c < 3; c++) {
            if (actc[c]) {
                float g4[4];
#pragma unroll
                for (int g = 0; g < 4; g++) {
                    int r = g * UT + duc[c];
                    u64 s0 = gp64[(0 * BT + bl[c]) * GPSU + r];
                    u64 s1 = gp64[(1 * BT + bl[c]) * GPSU + r];
                    float2 f = unpack2(add2(s0, s1));
                    g4[g] = f.x + f.y + bs[c][g] + pfA[c][g] + pfB[c][g];
                }
                float ig = fsig(g4[0]);
                float fg = fsig(g4[1]);
                float gg = 2.f * fsig(2.f * g4[2]) - 1.f;   // tanh
                float og = fsig(g4[3]);
                cr[c] = fg * cr[c] + ig * gg;
                float hv = og * (2.f * fsig(2.f * cr[c]) - 1.f);
                hx_out[hoff[c]] = hv;
                hs[c] += hv;
            }
        }
        __syncthreads();   // hout written + gp consumed before release/reuse

        // ---- warp0 only: release, poll group, issue next TMAs ----
        if (t + 1 < T_SZ && wrp == 0) {
            if (lane == 0) { __threadfence(); st_rel(&d_arrive[bt][ut], (u32)(t + 1)); }
            if (lane < 15) {
                while (ld_acq(&d_arrive[bt][lane]) < (u32)(t + 1)) {}
            }
            __syncwarp();
            if (lane == 0) {
                mbar_expect_tx(mbar_lo, HBLKB);
                bulk_cp_g2s(hsm_s, hx_out + (long long)bt * HBLK,
                            HBLKB, mbar_lo);
                mbar_expect_tx(mbar_hi, HBLKB);
                bulk_cp_g2s(hsm_s + HBLKB, hx_out + (long long)(8 + bt) * HBLK,
                            HBLKB, mbar_hi);
            }
        }
        // warps 1-7 fall through; next iteration's mbar_wait gates them
    }

    // ---- write hidden-state sums for the classifier ----
#pragma unroll
    for (int c = 0; c < 3; c++) {
        if (actc[c])
            hsum[(b0c + bl[c]) * HID + u0 + duc[c]] = hs[c];
    }
}

// ---------------- classifier head: mean-pool -> dense(100) -> dense(5) -> LSM
__global__ void classifier(const float* __restrict__ hsum,
                           const float* __restrict__ W1, const float* __restrict__ b1,
                           const float* __restrict__ W2, const float* __restrict__ b2,
                           float* __restrict__ out) {
    int b = blockIdx.x;
    int tid = threadIdx.x;   // 128
    __shared__ float pooled[HID];
    __shared__ float l1s[100];
    __shared__ float l2s[NCLS];

    for (int i = tid; i < HID; i += blockDim.x)
        pooled[i] = hsum[b * HID + i] * (1.f / (float)T_SZ);
    __syncthreads();

    if (tid < 100) {
        float s = b1[tid];
        const float* wr = W1 + tid * HID;
#pragma unroll 4
        for (int k = 0; k < HID; k++) s = fmaf(pooled[k], wr[k], s);
        l1s[tid] = 1.f / (1.f + expf(-s));
    }
    __syncthreads();

    if (tid < NCLS) {
        float s = b2[tid];
        const float* wr = W2 + tid * 100;
#pragma unroll 4
        for (int k = 0; k < 100; k++) s = fmaf(l1s[k], wr[k], s);
        l2s[tid] = 1.f / (1.f + expf(-s));
    }
    __syncthreads();

    if (tid < NCLS) {
        float m = l2s[0];
#pragma unroll
        for (int j = 1; j < NCLS; j++) m = fmaxf(m, l2s[j]);
        float sum = 0.f;
#pragma unroll
        for (int j = 0; j < NCLS; j++) sum += expf(l2s[j] - m);
        out[b * NCLS + tid] = l2s[tid] - m - logf(sum);
    }
}

// ------------------------------ launch ---------------------------------------
extern "C" void kernel_launch(void* const* d_in, const int* in_sizes, int n_in,
                              void* d_out, int out_size) {
    const int*   ids  = nullptr;
    const float* glove = nullptr, *W_ih = nullptr, *W_hh = nullptr;
    const float* b_ih = nullptr, *b_hh = nullptr;
    const float* W1 = nullptr, *b1 = nullptr, *W2 = nullptr, *b2 = nullptr;

    for (int i = 0; i < n_in; i++) {
        switch (in_sizes[i]) {
            case B_SZ * T_SZ:      ids   = (const int*)d_in[i];   break;
            case VOCAB * EMB:      glove = (const float*)d_in[i]; break;
            case GATES * 600:      W_ih  = (const float*)d_in[i]; break;
            case GATES * HID:      W_hh  = (const float*)d_in[i]; break;
            case GATES:            if (!b_ih) b_ih = (const float*)d_in[i];
                                   else       b_hh = (const float*)d_in[i]; break;
            case 100 * HID:        W1 = (const float*)d_in[i]; break;
            case 100:              b1 = (const float*)d_in[i]; break;
            case NCLS * 100:       W2 = (const float*)d_in[i]; break;
            case NCLS:             b2 = (const float*)d_in[i]; break;
            default: break; // size-1 scalar (max_num_of_words) ignored
        }
    }
    if (!ids || !glove || !W_ih || !W_hh || !b_ih || !b_hh || !W1 || !b1 || !W2 || !b2)
        return;

    float *P, *Wcat, *hx, *hsum;
    cudaGetSymbolAddress((void**)&P,    d_P);
    cudaGetSymbolAddress((void**)&Wcat, d_Wcat);
    cudaGetSymbolAddress((void**)&hx,   d_hx);
    cudaGetSymbolAddress((void**)&hsum, d_hsum);

    static bool attr_done = false;
    if (!attr_done) {
        cudaFuncSetAttribute(lstm_persistent,
                             cudaFuncAttributeMaxDynamicSharedMemorySize,
                             SM_BYTES);
        attr_done = true;
    }

    // 1) repack W_ih, zero h-exchange + flags       [1 node]
    prep_kernel<<<(PCOLS * EMB + 255) / 256, 256>>>(W_ih, Wcat, hx);

    // 2) vocabulary projection P = glove @ Wcat^T   [1 node]
    {
        dim3 grid((PCOLS + TILE - 1) / TILE, (VOCAB + TILE - 1) / TILE, 1);
        sgemm_f2<<<grid, 256>>>(glove, Wcat, P,
                                VOCAB, PCOLS, EMB, EMB, EMB, PCOLS);
    }

    // 3) whole 512-step LSTM in one persistent kernel [1 node]
    lstm_persistent<<<NCTA, 256, SM_BYTES>>>(
        W_hh, P, ids, b_ih, b_hh, hx, hsum);

    // 4) classifier head                            [1 node]
    classifier<<<B_SZ, 128>>>(hsum, W1, b1, W2, b2, (float*)d_out);
}